// round 2
// baseline (speedup 1.0000x reference)
#include <cuda_runtime.h>
#include <cstdint>

// Fixed shapes per reference
static constexpr int Bn    = 512;     // batch
static constexpr int Ln    = 8192;    // doc length
static constexpr int Nn    = 128;     // output_sentence_num
static constexpr int Sn    = 256;     // output_sentence_len
static constexpr int DELIM = 5;
static constexpr int TPB   = 256;     // threads per block
static constexpr int TOKS  = Ln / TPB; // 32 tokens per thread (8 x int4)
static constexpr int NW    = TPB / 32; // 8 warps

// d_out layout (float32): [ otp(B*N*S) | len_doc(B) | mask(B*N*S) ]
__global__ __launch_bounds__(TPB, 6)
void split_kernel(const int* __restrict__ x, float* __restrict__ out)
{
    __shared__ int s_row[Ln];        // full row staged (32 KB)
    __shared__ int s_dpos[Nn - 1];   // positions of first 127 delimiters
    __shared__ int s_woff[NW];       // per-warp scan offsets
    __shared__ int s_D;              // total delimiter count
    __shared__ int s_doc;            // # nonempty sentences

    const int b    = blockIdx.x;
    const int t    = threadIdx.x;
    const int lane = t & 31;
    const int warp = t >> 5;

    if (t == 0) s_doc = 0;

    const int* __restrict__ xrow = x + (size_t)b * Ln;

    // ---- Pass 1: load 32 tokens (8 x int4), stage to smem, count delimiters ----
    const int base = t * TOKS;
    const int4* x4 = reinterpret_cast<const int4*>(xrow + base);
    int4* s4 = reinterpret_cast<int4*>(s_row + base);

    int cnt = 0;
    #pragma unroll
    for (int i = 0; i < TOKS / 4; i++) {
        int4 v = x4[i];
        s4[i] = v;
        cnt += (v.x == DELIM) + (v.y == DELIM) + (v.z == DELIM) + (v.w == DELIM);
    }

    // warp inclusive scan of counts
    int incl = cnt;
    #pragma unroll
    for (int o = 1; o < 32; o <<= 1) {
        int n = __shfl_up_sync(0xffffffffu, incl, o);
        if (lane >= o) incl += n;
    }
    if (lane == 31) s_woff[warp] = incl;
    __syncthreads();

    if (warp == 0 && lane < NW) {
        int my  = s_woff[lane];
        int inc = my;
        #pragma unroll
        for (int o = 1; o < NW; o <<= 1) {
            int n = __shfl_up_sync((1u << NW) - 1u, inc, o);
            if (lane >= o) inc += n;
        }
        s_woff[lane] = inc - my;      // exclusive warp offset
        if (lane == NW - 1) s_D = inc;
    }
    __syncthreads();

    const int excl = incl - cnt + s_woff[warp];

    // ---- Pass 2: record first 127 delimiter positions (reread from smem) ----
    if (cnt > 0 && excl < Nn - 1) {
        int r = excl;
        #pragma unroll 4
        for (int i = 0; i < TOKS; i++) {
            if (s_row[base + i] == DELIM) {
                if (r < Nn - 1) s_dpos[r] = base + i;
                if (++r >= Nn - 1) break;
            }
        }
    }
    __syncthreads();

    const int D = s_D;

    float* __restrict__ otp_f  = out;
    float* __restrict__ len_f  = out + (size_t)Bn * Nn * Sn;
    float* __restrict__ mask_f = len_f + Bn;

    // ---- Emit: one warp per segment, float4 stores ----
    int doc_local = 0;
    #pragma unroll 1
    for (int k = warp; k < Nn; k += NW) {
        int start = 0, size = 0;
        if (k <= D) {
            start = (k == 0) ? 0 : (s_dpos[k - 1] + 1);
            if (k == Nn - 1 || k == D) size = (Ln + 1) - start;  // tail / last used
            else                        size = s_dpos[k] + 1 - start;
        }
        const bool ws = (size > 1);   // lone-delimiter chunk -> all PAD

        const size_t row_off = ((size_t)b * Nn + k) * Sn;
        float4* __restrict__ otp4  = reinterpret_cast<float4*>(otp_f  + row_off);
        float4* __restrict__ mask4 = reinterpret_cast<float4*>(mask_f + row_off);

        int nz = 0;
        #pragma unroll
        for (int i = 0; i < Sn / 128; i++) {          // 2 iters
            const int s0 = i * 128 + lane * 4;
            int v0 = 0, v1 = 0, v2 = 0, v3 = 0;
            if (ws && s0 < size) {
                const int j = start + s0;
                v0 = (j     < Ln) ? s_row[j]     : DELIM;
                if (s0 + 1 < size) v1 = (j + 1 < Ln) ? s_row[j + 1] : DELIM;
                if (s0 + 2 < size) v2 = (j + 2 < Ln) ? s_row[j + 2] : DELIM;
                if (s0 + 3 < size) v3 = (j + 3 < Ln) ? s_row[j + 3] : DELIM;
            }
            nz += (v0 != 0) + (v1 != 0) + (v2 != 0) + (v3 != 0);
            otp4[i * 32 + lane] =
                make_float4((float)v0, (float)v1, (float)v2, (float)v3);
        }

        // warp-reduce nonzero count -> len_sent for this segment
        #pragma unroll
        for (int o = 16; o > 0; o >>= 1) nz += __shfl_down_sync(0xffffffffu, nz, o);
        nz = __shfl_sync(0xffffffffu, nz, 0);
        if (lane == 0 && nz > 0) doc_local++;

        #pragma unroll
        for (int i = 0; i < Sn / 128; i++) {
            const int s0 = i * 128 + lane * 4;
            mask4[i * 32 + lane] = make_float4(
                (s0     < nz) ? 1.0f : 0.0f,
                (s0 + 1 < nz) ? 1.0f : 0.0f,
                (s0 + 2 < nz) ? 1.0f : 0.0f,
                (s0 + 3 < nz) ? 1.0f : 0.0f);
        }
    }

    if (lane == 0 && doc_local > 0) atomicAdd(&s_doc, doc_local);
    __syncthreads();
    if (t == 0) len_f[b] = (float)s_doc;
}

extern "C" void kernel_launch(void* const* d_in, const int* in_sizes, int n_in,
                              void* d_out, int out_size)
{
    const int* x = (const int*)d_in[0];
    split_kernel<<<Bn, TPB>>>(x, (float*)d_out);
}

// round 3
// speedup vs baseline: 1.2885x; 1.2885x over previous
#include <cuda_runtime.h>
#include <cstdint>

// Fixed shapes per reference
static constexpr int Bn    = 512;      // batch
static constexpr int Ln    = 8192;     // doc length
static constexpr int Nn    = 128;      // output_sentence_num
static constexpr int Sn    = 256;      // output_sentence_len
static constexpr int DELIM = 5;
static constexpr int TPB   = 256;      // threads per block
static constexpr int TOKS  = Ln / TPB; // 32 tokens per thread == 1 bitmask word
static constexpr int NW    = TPB / 32; // 8 warps

// d_out (float32): [ otp(B*N*S) | len_doc(B) | mask(B*N*S) ]
__global__ __launch_bounds__(TPB, 6)
void split_kernel(const int* __restrict__ x, float* __restrict__ out)
{
    __shared__ int s_dpos[Nn - 1];   // positions of first 127 delimiters
    __shared__ int s_woff[NW];       // per-warp scan offsets
    __shared__ int s_D;              // total delimiter count
    __shared__ int s_doc;            // # nonempty sentences

    const int b    = blockIdx.x;
    const int t    = threadIdx.x;
    const int lane = t & 31;
    const int warp = t >> 5;

    if (t == 0) s_doc = 0;

    const int* __restrict__ xrow = x + (size_t)b * Ln;

    // ---- Pass 1: load 32 tokens (8 x int4), build delimiter bitmask ----
    const int base = t * TOKS;
    const int4* __restrict__ x4 = reinterpret_cast<const int4*>(xrow + base);

    unsigned dmask = 0;
    #pragma unroll
    for (int i = 0; i < TOKS / 4; i++) {
        int4 v = x4[i];
        dmask |= (unsigned)(v.x == DELIM) << (4 * i + 0);
        dmask |= (unsigned)(v.y == DELIM) << (4 * i + 1);
        dmask |= (unsigned)(v.z == DELIM) << (4 * i + 2);
        dmask |= (unsigned)(v.w == DELIM) << (4 * i + 3);
    }
    const int cnt = __popc(dmask);

    // warp inclusive scan of counts
    int incl = cnt;
    #pragma unroll
    for (int o = 1; o < 32; o <<= 1) {
        int n = __shfl_up_sync(0xffffffffu, incl, o);
        if (lane >= o) incl += n;
    }
    if (lane == 31) s_woff[warp] = incl;
    __syncthreads();

    if (warp == 0 && lane < NW) {
        int my  = s_woff[lane];
        int inc = my;
        #pragma unroll
        for (int o = 1; o < NW; o <<= 1) {
            int n = __shfl_up_sync((1u << NW) - 1u, inc, o);
            if (lane >= o) inc += n;
        }
        s_woff[lane] = inc - my;      // exclusive warp offset
        if (lane == NW - 1) s_D = inc;
    }
    __syncthreads();

    const int excl = incl - cnt + s_woff[warp];

    // ---- Pass 2: record first 127 delimiter positions from the bitmask ----
    if (dmask && excl < Nn - 1) {
        int r = excl;
        unsigned m = dmask;
        while (m && r < Nn - 1) {
            int bit = __ffs(m) - 1;
            s_dpos[r++] = base + bit;
            m &= m - 1;
        }
    }
    __syncthreads();

    const int D = s_D;

    float* __restrict__ otp_f  = out;
    float* __restrict__ len_f  = out + (size_t)Bn * Nn * Sn;
    float* __restrict__ mask_f = len_f + Bn;

    // ---- Emit: one warp per segment, float4 stores, scalar L1-hit reads ----
    int doc_local = 0;
    #pragma unroll 1
    for (int k = warp; k < Nn; k += NW) {
        int start = 0, size = 0;
        if (k <= D) {
            start = (k == 0) ? 0 : (s_dpos[k - 1] + 1);
            if (k == Nn - 1 || k == D) size = (Ln + 1) - start;  // tail-merged / last
            else                        size = s_dpos[k] + 1 - start;
        }
        const bool ws = (size > 1);   // lone-delimiter chunk -> all PAD

        const size_t row_off = ((size_t)b * Nn + k) * Sn;
        float4* __restrict__ otp4  = reinterpret_cast<float4*>(otp_f  + row_off);
        float4* __restrict__ mask4 = reinterpret_cast<float4*>(mask_f + row_off);

        int nz = 0;
        #pragma unroll
        for (int i = 0; i < Sn / 128; i++) {          // 2 iters of 128 slots
            const int s0 = i * 128 + lane * 4;
            int v0 = 0, v1 = 0, v2 = 0, v3 = 0;
            if (ws && s0 < size) {
                const int j = start + s0;
                v0 = (j     < Ln) ? xrow[j]     : DELIM;
                if (s0 + 1 < size) v1 = (j + 1 < Ln) ? xrow[j + 1] : DELIM;
                if (s0 + 2 < size) v2 = (j + 2 < Ln) ? xrow[j + 2] : DELIM;
                if (s0 + 3 < size) v3 = (j + 3 < Ln) ? xrow[j + 3] : DELIM;
            }
            nz += (v0 != 0) + (v1 != 0) + (v2 != 0) + (v3 != 0);
            otp4[i * 32 + lane] =
                make_float4((float)v0, (float)v1, (float)v2, (float)v3);
        }

        // warp-reduce nonzero count -> len_sent
        #pragma unroll
        for (int o = 16; o > 0; o >>= 1) nz += __shfl_down_sync(0xffffffffu, nz, o);
        nz = __shfl_sync(0xffffffffu, nz, 0);
        if (lane == 0 && nz > 0) doc_local++;

        #pragma unroll
        for (int i = 0; i < Sn / 128; i++) {
            const int s0 = i * 128 + lane * 4;
            mask4[i * 32 + lane] = make_float4(
                (s0     < nz) ? 1.0f : 0.0f,
                (s0 + 1 < nz) ? 1.0f : 0.0f,
                (s0 + 2 < nz) ? 1.0f : 0.0f,
                (s0 + 3 < nz) ? 1.0f : 0.0f);
        }
    }

    if (lane == 0 && doc_local > 0) atomicAdd(&s_doc, doc_local);
    __syncthreads();
    if (t == 0) len_f[b] = (float)s_doc;
}

extern "C" void kernel_launch(void* const* d_in, const int* in_sizes, int n_in,
                              void* d_out, int out_size)
{
    const int* x = (const int*)d_in[0];
    split_kernel<<<Bn, TPB>>>(x, (float*)d_out);
}